// round 16
// baseline (speedup 1.0000x reference)
#include <cuda_runtime.h>
#include <cuda_fp16.h>

#define INV_SCALE 0.35355339059327373f
#define SCENE_INV (1.0f / 1.5f)
#define NBINS 512               // 8x8x8 bins of 16^3 voxels
#define PT_CAP 2000000

// ---------------- scratch (static device globals; no allocation) ----------------
__device__ float  g_vol32[28 * 32 * 32 * 32];               // 3.5 MB
__device__ float  g_vol64[28 * 64 * 64 * 64];               // 28 MB
__device__ __half g_vol128h[128 * 128 * 128 * 32];          // 128 MB channel-last fp16
__device__ int    g_hist[NBINS];
__device__ int    g_cursor[NBINS];
__device__ float4 g_pts[PT_CAP];                            // (px,py,pz, orig_idx bits)

// ---------------- levels 0/1: channel-first IDWT (fp32) ----------------
template <int D, bool FIRST>
__global__ void idwt_cf_kernel(const float* __restrict__ ap_ext,
                               const float* __restrict__ det) {
    const int C = 28;
    const int total = C * D * D * D;
    int tid = blockIdx.x * blockDim.x + threadIdx.x;
    if (tid >= total) return;

    const float* src = FIRST ? ap_ext : g_vol32;
    float* dst = FIRST ? g_vol32 : g_vol64;

    int k = tid % D;
    int t = tid / D;
    int j = t % D; t /= D;
    int i = t % D;
    int c = t / D;

    const int sub = C * D * D * D;
    float a0 = src[tid];
    float a1 = det[0 * sub + tid];
    float a2 = det[1 * sub + tid];
    float a3 = det[2 * sub + tid];
    float a4 = det[3 * sub + tid];
    float a5 = det[4 * sub + tid];
    float a6 = det[5 * sub + tid];
    float a7 = det[6 * sub + tid];

    float u0 = a0 + a4, u4 = a0 - a4;
    float u1 = a1 + a5, u5 = a1 - a5;
    float u2 = a2 + a6, u6 = a2 - a6;
    float u3 = a3 + a7, u7 = a3 - a7;
    float m0 = u0 + u2, m2 = u0 - u2;
    float m1 = u1 + u3, m3 = u1 - u3;
    float m4 = u4 + u6, m6 = u4 - u6;
    float m5 = u5 + u7, m7 = u5 - u7;
    float o000 = (m0 + m1) * INV_SCALE;
    float o001 = (m0 - m1) * INV_SCALE;
    float o010 = (m2 + m3) * INV_SCALE;
    float o011 = (m2 - m3) * INV_SCALE;
    float o100 = (m4 + m5) * INV_SCALE;
    float o101 = (m4 - m5) * INV_SCALE;
    float o110 = (m6 + m7) * INV_SCALE;
    float o111 = (m6 - m7) * INV_SCALE;

    const int OD = 2 * D;
    size_t base = (((size_t)c * OD + 2 * i) * OD + (2 * j)) * OD + 2 * k;
    size_t rowY = OD;
    size_t rowZ = (size_t)OD * OD;
    *reinterpret_cast<float2*>(dst + base)               = make_float2(o000, o001);
    *reinterpret_cast<float2*>(dst + base + rowY)        = make_float2(o010, o011);
    *reinterpret_cast<float2*>(dst + base + rowZ)        = make_float2(o100, o101);
    *reinterpret_cast<float2*>(dst + base + rowZ + rowY) = make_float2(o110, o111);
}

// ---------------- level 2: IDWT -> channel-last fp16 volume ----------------
// Block = input tile (i, j, k0..k0+15), all 28 channels.
// float4 staging loads, per-thread full 2x2x2 butterfly (16 LDS -> 16 outputs),
// smem output transpose so global stores are STG.128.
__global__ void __launch_bounds__(256) idwt_cl_kernel(const float* __restrict__ det) {
    __shared__ float sub[8][16][29];      // [subband][k][channel]
    __shared__ __half2 sOut[8 * 16 * 16]; // [m][k][cpair], 8KB
    const int D = 64;
    const int i = blockIdx.z;
    const int j = blockIdx.y;
    const int k0 = blockIdx.x * 16;
    const int t = threadIdx.x;
    const int subsz = 28 * D * D * D;

    // staging: 8 subbands x 28 ch x 4 float4 = 896 vector loads
    for (int l = t; l < 8 * 28 * 4; l += 256) {
        int s = l / 112;
        int rem = l - s * 112;
        int c = rem >> 2;
        int kq = rem & 3;
        int gidx = ((c * D + i) * D + j) * D + k0 + kq * 4;
        const float* srcp = (s == 0) ? (g_vol64 + gidx)
                                     : (det + (size_t)(s - 1) * subsz + gidx);
        float4 v = *reinterpret_cast<const float4*>(srcp);
        sub[s][kq * 4 + 0][c] = v.x;
        sub[s][kq * 4 + 1][c] = v.y;
        sub[s][kq * 4 + 2][c] = v.z;
        sub[s][kq * 4 + 3][c] = v.w;
    }
    __syncthreads();

    const int k = t >> 4;       // 0..15
    const int cpair = t & 15;   // 0..15
    const int c0 = 2 * cpair;

    float oc[2][8];
#pragma unroll
    for (int cc = 0; cc < 2; ++cc) {
        int c = c0 + cc;
        float a0 = 0.f, a1 = 0.f, a2 = 0.f, a3 = 0.f;
        float a4 = 0.f, a5 = 0.f, a6 = 0.f, a7 = 0.f;
        if (c < 28) {
            a0 = sub[0][k][c]; a1 = sub[1][k][c];
            a2 = sub[2][k][c]; a3 = sub[3][k][c];
            a4 = sub[4][k][c]; a5 = sub[5][k][c];
            a6 = sub[6][k][c]; a7 = sub[7][k][c];
        }
        float w0p = a0 + a1, w0m = a0 - a1;
        float w1p = a2 + a3, w1m = a2 - a3;
        float w2p = a4 + a5, w2m = a4 - a5;
        float w3p = a6 + a7, w3m = a6 - a7;
        float s01 = w0p + w1p, d01 = w0p - w1p;
        float s23 = w2p + w3p, d23 = w2p - w3p;
        float s01m = w0m + w1m, d01m = w0m - w1m;
        float s23m = w2m + w3m, d23m = w2m - w3m;
        oc[cc][0] = (s01 + s23) * INV_SCALE;
        oc[cc][1] = (s01m + s23m) * INV_SCALE;
        oc[cc][2] = (d01 + d23) * INV_SCALE;
        oc[cc][3] = (d01m + d23m) * INV_SCALE;
        oc[cc][4] = (s01 - s23) * INV_SCALE;
        oc[cc][5] = (s01m - s23m) * INV_SCALE;
        oc[cc][6] = (d01 - d23) * INV_SCALE;
        oc[cc][7] = (d01m - d23m) * INV_SCALE;
    }

#pragma unroll
    for (int m = 0; m < 8; ++m)
        sOut[m * 256 + k * 16 + cpair] = __floats2half2_rn(oc[0][m], oc[1][m]);
    __syncthreads();

    // 512 x 16B coalesced stores
    uint4* g4 = reinterpret_cast<uint4*>(g_vol128h);
    const uint4* s4 = reinterpret_cast<const uint4*>(sOut);
#pragma unroll
    for (int it = 0; it < 2; ++it) {
        int idx = t + it * 256;
        int quad = idx & 3;
        int kk = (idx >> 2) & 15;
        int m = idx >> 6;
        int p = m >> 2, q = (m >> 1) & 1, r = m & 1;
        int z = 2 * i + p, y = 2 * j + q, x = 2 * (k0 + kk) + r;
        size_t rec = ((size_t)z * 128 + y) * 128 + x;
        g4[rec * 4 + quad] = s4[idx];
    }
}

// ---------------- point binning (counting sort over 512 spatial bins) ----------------
__device__ __forceinline__ int bin_key(float px, float py, float pz) {
    int bx = min(max((int)px, 0), 127) >> 4;
    int by = min(max((int)py, 0), 127) >> 4;
    int bz = min(max((int)pz, 0), 127) >> 4;
    return (bz << 6) | (by << 3) | bx;
}

__global__ void zero_hist_kernel() {
    int t = threadIdx.x;
    if (t < NBINS) g_hist[t] = 0;
}

__global__ void hist_kernel(const float* __restrict__ xyz, int N) {
    int n = blockIdx.x * blockDim.x + threadIdx.x;
    if (n >= N) return;
    float px = (xyz[3 * n + 0] * SCENE_INV + 1.0f) * 0.5f * 127.0f;
    float py = (xyz[3 * n + 1] * SCENE_INV + 1.0f) * 0.5f * 127.0f;
    float pz = (xyz[3 * n + 2] * SCENE_INV + 1.0f) * 0.5f * 127.0f;
    atomicAdd(&g_hist[bin_key(px, py, pz)], 1);
}

__global__ void scan_kernel() {
    __shared__ int tmp[NBINS];
    int t = threadIdx.x;
    int orig = g_hist[t];
    tmp[t] = orig;
    __syncthreads();
    for (int off = 1; off < NBINS; off <<= 1) {
        int v = (t >= off) ? tmp[t - off] : 0;
        __syncthreads();
        tmp[t] += v;
        __syncthreads();
    }
    g_cursor[t] = tmp[t] - orig;   // exclusive prefix
}

__global__ void scatter_kernel(const float* __restrict__ xyz, int N) {
    int n = blockIdx.x * blockDim.x + threadIdx.x;
    if (n >= N) return;
    float px = (xyz[3 * n + 0] * SCENE_INV + 1.0f) * 0.5f * 127.0f;
    float py = (xyz[3 * n + 1] * SCENE_INV + 1.0f) * 0.5f * 127.0f;
    float pz = (xyz[3 * n + 2] * SCENE_INV + 1.0f) * 0.5f * 127.0f;
    int pos = atomicAdd(&g_cursor[bin_key(px, py, pz)], 1);
    g_pts[pos] = make_float4(px, py, pz, __int_as_float(n));
}

// ---------------- trilinear query on binned points (2 threads per point) ----------------
__device__ __forceinline__ void acc_pair(float& a0, float& a1, unsigned u, float w) {
    __half2 hh = *reinterpret_cast<__half2*>(&u);
    float2 f = __half22float2(hh);
    a0 = fmaf(w, f.x, a0);
    a1 = fmaf(w, f.y, a1);
}

__global__ void __launch_bounds__(256) query_kernel3(float* __restrict__ out, int N) {
    const int t = threadIdx.x;
    const int pos = blockIdx.x * 128 + (t >> 1);
    const int h = t & 1;                   // h=0: ch 0..15, h=1: ch 16..27
    if (pos >= N) return;

    float4 pt = g_pts[pos];
    float px = pt.x, py = pt.y, pz = pt.z;
    int n = __float_as_int(pt.w);

    float flx = floorf(px), fly = floorf(py), flz = floorf(pz);
    int ix0 = (int)flx, iy0 = (int)fly, iz0 = (int)flz;
    float fx = px - flx, fy = py - fly, fz = pz - flz;

    float vx0 = (ix0 >= 0 && ix0 < 128) ? 1.0f : 0.0f;
    float vx1 = (ix0 + 1 >= 0 && ix0 + 1 < 128) ? 1.0f : 0.0f;
    float vy0 = (iy0 >= 0 && iy0 < 128) ? 1.0f : 0.0f;
    float vy1 = (iy0 + 1 >= 0 && iy0 + 1 < 128) ? 1.0f : 0.0f;
    float vz0 = (iz0 >= 0 && iz0 < 128) ? 1.0f : 0.0f;
    float vz1 = (iz0 + 1 >= 0 && iz0 + 1 < 128) ? 1.0f : 0.0f;

    int x0 = min(max(ix0, 0), 127), x1 = min(max(ix0 + 1, 0), 127);
    int y0 = min(max(iy0, 0), 127), y1 = min(max(iy0 + 1, 0), 127);
    int z0 = min(max(iz0, 0), 127), z1 = min(max(iz0 + 1, 0), 127);

    float wx0 = (1.0f - fx) * vx0, wx1 = fx * vx1;
    float wy0 = (1.0f - fy) * vy0, wy1 = fy * vy1;
    float wz0 = (1.0f - fz) * vz0, wz1 = fz * vz1;

    float acc[16];
#pragma unroll
    for (int c = 0; c < 16; ++c) acc[c] = 0.0f;

    const __half* volBase = g_vol128h + h * 16;

#pragma unroll
    for (int dz = 0; dz < 2; ++dz) {
        int zz = dz ? z1 : z0;
        float wz = dz ? wz1 : wz0;
#pragma unroll
        for (int dy = 0; dy < 2; ++dy) {
            int yy = dy ? y1 : y0;
            float wzy = wz * (dy ? wy1 : wy0);
#pragma unroll
            for (int dx = 0; dx < 2; ++dx) {
                int xx = dx ? x1 : x0;
                float w = wzy * (dx ? wx1 : wx0);
                const uint4* p4 = reinterpret_cast<const uint4*>(
                    volBase + (((size_t)zz * 128 + yy) * 128 + xx) * 32);
                uint4 va = __ldg(p4 + 0);
                uint4 vb = __ldg(p4 + 1);
                acc_pair(acc[0],  acc[1],  va.x, w);
                acc_pair(acc[2],  acc[3],  va.y, w);
                acc_pair(acc[4],  acc[5],  va.z, w);
                acc_pair(acc[6],  acc[7],  va.w, w);
                acc_pair(acc[8],  acc[9],  vb.x, w);
                acc_pair(acc[10], acc[11], vb.y, w);
                acc_pair(acc[12], acc[13], vb.z, w);
                acc_pair(acc[14], acc[15], vb.w, w);   // pad for h=1 (discarded)
            }
        }
    }

    // direct store: 112B contiguous per point (16B aligned)
    float* row = out + (size_t)n * 28;
    if (h == 0) {
        float4* o4 = reinterpret_cast<float4*>(row);
        o4[0] = make_float4(acc[0],  acc[1],  acc[2],  acc[3]);
        o4[1] = make_float4(acc[4],  acc[5],  acc[6],  acc[7]);
        o4[2] = make_float4(acc[8],  acc[9],  acc[10], acc[11]);
        o4[3] = make_float4(acc[12], acc[13], acc[14], acc[15]);
    } else {
        float4* o4 = reinterpret_cast<float4*>(row + 16);
        o4[0] = make_float4(acc[0],  acc[1],  acc[2],  acc[3]);
        o4[1] = make_float4(acc[4],  acc[5],  acc[6],  acc[7]);
        o4[2] = make_float4(acc[8],  acc[9],  acc[10], acc[11]);
    }
}

extern "C" void kernel_launch(void* const* d_in, const int* in_sizes, int n_in,
                              void* d_out, int out_size) {
    const float* approx = (const float*)d_in[0];
    const float* det0 = (const float*)d_in[1];
    const float* det1 = (const float*)d_in[2];
    const float* det2 = (const float*)d_in[3];
    const float* xyz = (const float*)d_in[4];
    float* out = (float*)d_out;
    int N = in_sizes[4] / 3;

    // IDWT chain
    idwt_cf_kernel<16, true><<<(28 * 16 * 16 * 16 + 255) / 256, 256>>>(approx, det0);
    idwt_cf_kernel<32, false><<<(28 * 32 * 32 * 32 + 255) / 256, 256>>>(nullptr, det1);
    dim3 g2(4, 64, 64);
    idwt_cl_kernel<<<g2, 256>>>(det2);

    // spatial binning of query points
    zero_hist_kernel<<<1, NBINS>>>();
    hist_kernel<<<(N + 255) / 256, 256>>>(xyz, N);
    scan_kernel<<<1, NBINS>>>();
    scatter_kernel<<<(N + 255) / 256, 256>>>(xyz, N);

    // query in binned order
    query_kernel3<<<(N + 127) / 128, 256>>>(out, N);
}

// round 17
// speedup vs baseline: 1.9762x; 1.9762x over previous
#include <cuda_runtime.h>
#include <cuda_fp16.h>

#define INV_SCALE 0.35355339059327373f
#define SCENE_INV (1.0f / 1.5f)
#define NBINS 512               // 8x8x8 bins of 16^3 voxels
#define BIN_STRIDE 521          // ints; 2084B between counters -> spreads LTS slices
#define PT_CAP 2000000

// ---------------- scratch (static device globals; no allocation) ----------------
__device__ float  g_vol32[28 * 32 * 32 * 32];               // 3.5 MB
__device__ float  g_vol64[28 * 64 * 64 * 64];               // 28 MB
__device__ __half g_vol128h[128 * 128 * 128 * 32];          // 128 MB channel-last fp16
__device__ int    g_histPad[NBINS * BIN_STRIDE];            // strided counters (~1 MB)
__device__ int    g_curPad[NBINS * BIN_STRIDE];             // strided cursors  (~1 MB)
__device__ float4 g_pts[PT_CAP];                            // (px,py,pz, orig_idx bits)

// ---------------- levels 0/1: channel-first IDWT (fp32) ----------------
template <int D, bool FIRST>
__global__ void idwt_cf_kernel(const float* __restrict__ ap_ext,
                               const float* __restrict__ det) {
    const int C = 28;
    const int total = C * D * D * D;
    int tid = blockIdx.x * blockDim.x + threadIdx.x;
    if (tid >= total) return;

    const float* src = FIRST ? ap_ext : g_vol32;
    float* dst = FIRST ? g_vol32 : g_vol64;

    int k = tid % D;
    int t = tid / D;
    int j = t % D; t /= D;
    int i = t % D;
    int c = t / D;

    const int sub = C * D * D * D;
    float a0 = src[tid];
    float a1 = det[0 * sub + tid];
    float a2 = det[1 * sub + tid];
    float a3 = det[2 * sub + tid];
    float a4 = det[3 * sub + tid];
    float a5 = det[4 * sub + tid];
    float a6 = det[5 * sub + tid];
    float a7 = det[6 * sub + tid];

    float u0 = a0 + a4, u4 = a0 - a4;
    float u1 = a1 + a5, u5 = a1 - a5;
    float u2 = a2 + a6, u6 = a2 - a6;
    float u3 = a3 + a7, u7 = a3 - a7;
    float m0 = u0 + u2, m2 = u0 - u2;
    float m1 = u1 + u3, m3 = u1 - u3;
    float m4 = u4 + u6, m6 = u4 - u6;
    float m5 = u5 + u7, m7 = u5 - u7;
    float o000 = (m0 + m1) * INV_SCALE;
    float o001 = (m0 - m1) * INV_SCALE;
    float o010 = (m2 + m3) * INV_SCALE;
    float o011 = (m2 - m3) * INV_SCALE;
    float o100 = (m4 + m5) * INV_SCALE;
    float o101 = (m4 - m5) * INV_SCALE;
    float o110 = (m6 + m7) * INV_SCALE;
    float o111 = (m6 - m7) * INV_SCALE;

    const int OD = 2 * D;
    size_t base = (((size_t)c * OD + 2 * i) * OD + (2 * j)) * OD + 2 * k;
    size_t rowY = OD;
    size_t rowZ = (size_t)OD * OD;
    *reinterpret_cast<float2*>(dst + base)               = make_float2(o000, o001);
    *reinterpret_cast<float2*>(dst + base + rowY)        = make_float2(o010, o011);
    *reinterpret_cast<float2*>(dst + base + rowZ)        = make_float2(o100, o101);
    *reinterpret_cast<float2*>(dst + base + rowZ + rowY) = make_float2(o110, o111);
}

// ---------------- level 2: IDWT -> channel-last fp16 volume ----------------
__global__ void __launch_bounds__(256) idwt_cl_kernel(const float* __restrict__ det) {
    __shared__ float sub[8][16][29];      // [subband][k][channel]
    __shared__ __half2 sOut[8 * 16 * 16]; // [m][k][cpair], 8KB
    const int D = 64;
    const int i = blockIdx.z;
    const int j = blockIdx.y;
    const int k0 = blockIdx.x * 16;
    const int t = threadIdx.x;
    const int subsz = 28 * D * D * D;

    for (int l = t; l < 8 * 28 * 4; l += 256) {
        int s = l / 112;
        int rem = l - s * 112;
        int c = rem >> 2;
        int kq = rem & 3;
        int gidx = ((c * D + i) * D + j) * D + k0 + kq * 4;
        const float* srcp = (s == 0) ? (g_vol64 + gidx)
                                     : (det + (size_t)(s - 1) * subsz + gidx);
        float4 v = *reinterpret_cast<const float4*>(srcp);
        sub[s][kq * 4 + 0][c] = v.x;
        sub[s][kq * 4 + 1][c] = v.y;
        sub[s][kq * 4 + 2][c] = v.z;
        sub[s][kq * 4 + 3][c] = v.w;
    }
    __syncthreads();

    const int k = t >> 4;       // 0..15
    const int cpair = t & 15;   // 0..15
    const int c0 = 2 * cpair;

    float oc[2][8];
#pragma unroll
    for (int cc = 0; cc < 2; ++cc) {
        int c = c0 + cc;
        float a0 = 0.f, a1 = 0.f, a2 = 0.f, a3 = 0.f;
        float a4 = 0.f, a5 = 0.f, a6 = 0.f, a7 = 0.f;
        if (c < 28) {
            a0 = sub[0][k][c]; a1 = sub[1][k][c];
            a2 = sub[2][k][c]; a3 = sub[3][k][c];
            a4 = sub[4][k][c]; a5 = sub[5][k][c];
            a6 = sub[6][k][c]; a7 = sub[7][k][c];
        }
        float w0p = a0 + a1, w0m = a0 - a1;
        float w1p = a2 + a3, w1m = a2 - a3;
        float w2p = a4 + a5, w2m = a4 - a5;
        float w3p = a6 + a7, w3m = a6 - a7;
        float s01 = w0p + w1p, d01 = w0p - w1p;
        float s23 = w2p + w3p, d23 = w2p - w3p;
        float s01m = w0m + w1m, d01m = w0m - w1m;
        float s23m = w2m + w3m, d23m = w2m - w3m;
        oc[cc][0] = (s01 + s23) * INV_SCALE;
        oc[cc][1] = (s01m + s23m) * INV_SCALE;
        oc[cc][2] = (d01 + d23) * INV_SCALE;
        oc[cc][3] = (d01m + d23m) * INV_SCALE;
        oc[cc][4] = (s01 - s23) * INV_SCALE;
        oc[cc][5] = (s01m - s23m) * INV_SCALE;
        oc[cc][6] = (d01 - d23) * INV_SCALE;
        oc[cc][7] = (d01m - d23m) * INV_SCALE;
    }

#pragma unroll
    for (int m = 0; m < 8; ++m)
        sOut[m * 256 + k * 16 + cpair] = __floats2half2_rn(oc[0][m], oc[1][m]);
    __syncthreads();

    uint4* g4 = reinterpret_cast<uint4*>(g_vol128h);
    const uint4* s4 = reinterpret_cast<const uint4*>(sOut);
#pragma unroll
    for (int it = 0; it < 2; ++it) {
        int idx = t + it * 256;
        int quad = idx & 3;
        int kk = (idx >> 2) & 15;
        int m = idx >> 6;
        int p = m >> 2, q = (m >> 1) & 1, r = m & 1;
        int z = 2 * i + p, y = 2 * j + q, x = 2 * (k0 + kk) + r;
        size_t rec = ((size_t)z * 128 + y) * 128 + x;
        g4[rec * 4 + quad] = s4[idx];
    }
}

// ---------------- point binning (slice-spread strided counters) ----------------
__device__ __forceinline__ int bin_key(float px, float py, float pz) {
    int bx = min(max((int)px, 0), 127) >> 4;
    int by = min(max((int)py, 0), 127) >> 4;
    int bz = min(max((int)pz, 0), 127) >> 4;
    return (bz << 6) | (by << 3) | bx;
}

__global__ void zero_hist_kernel() {
    int t = threadIdx.x;
    if (t < NBINS) g_histPad[t * BIN_STRIDE] = 0;
}

__global__ void hist_kernel(const float* __restrict__ xyz, int N) {
    int n = blockIdx.x * blockDim.x + threadIdx.x;
    if (n >= N) return;
    float px = (xyz[3 * n + 0] * SCENE_INV + 1.0f) * 0.5f * 127.0f;
    float py = (xyz[3 * n + 1] * SCENE_INV + 1.0f) * 0.5f * 127.0f;
    float pz = (xyz[3 * n + 2] * SCENE_INV + 1.0f) * 0.5f * 127.0f;
    atomicAdd(&g_histPad[bin_key(px, py, pz) * BIN_STRIDE], 1);
}

__global__ void scan_kernel() {
    __shared__ int tmp[NBINS];
    int t = threadIdx.x;
    int orig = g_histPad[t * BIN_STRIDE];
    tmp[t] = orig;
    __syncthreads();
    for (int off = 1; off < NBINS; off <<= 1) {
        int v = (t >= off) ? tmp[t - off] : 0;
        __syncthreads();
        tmp[t] += v;
        __syncthreads();
    }
    g_curPad[t * BIN_STRIDE] = tmp[t] - orig;   // exclusive prefix
}

__global__ void scatter_kernel(const float* __restrict__ xyz, int N) {
    int n = blockIdx.x * blockDim.x + threadIdx.x;
    if (n >= N) return;
    float px = (xyz[3 * n + 0] * SCENE_INV + 1.0f) * 0.5f * 127.0f;
    float py = (xyz[3 * n + 1] * SCENE_INV + 1.0f) * 0.5f * 127.0f;
    float pz = (xyz[3 * n + 2] * SCENE_INV + 1.0f) * 0.5f * 127.0f;
    int pos = atomicAdd(&g_curPad[bin_key(px, py, pz) * BIN_STRIDE], 1);
    g_pts[pos] = make_float4(px, py, pz, __int_as_float(n));
}

// ---------------- trilinear query on binned points (2 threads per point) ----------------
__device__ __forceinline__ void acc_pair(float& a0, float& a1, unsigned u, float w) {
    __half2 hh = *reinterpret_cast<__half2*>(&u);
    float2 f = __half22float2(hh);
    a0 = fmaf(w, f.x, a0);
    a1 = fmaf(w, f.y, a1);
}

__global__ void __launch_bounds__(256) query_kernel3(float* __restrict__ out, int N) {
    const int t = threadIdx.x;
    const int pos = blockIdx.x * 128 + (t >> 1);
    const int h = t & 1;                   // h=0: ch 0..15, h=1: ch 16..27
    if (pos >= N) return;

    float4 pt = g_pts[pos];
    float px = pt.x, py = pt.y, pz = pt.z;
    int n = __float_as_int(pt.w);

    float flx = floorf(px), fly = floorf(py), flz = floorf(pz);
    int ix0 = (int)flx, iy0 = (int)fly, iz0 = (int)flz;
    float fx = px - flx, fy = py - fly, fz = pz - flz;

    float vx0 = (ix0 >= 0 && ix0 < 128) ? 1.0f : 0.0f;
    float vx1 = (ix0 + 1 >= 0 && ix0 + 1 < 128) ? 1.0f : 0.0f;
    float vy0 = (iy0 >= 0 && iy0 < 128) ? 1.0f : 0.0f;
    float vy1 = (iy0 + 1 >= 0 && iy0 + 1 < 128) ? 1.0f : 0.0f;
    float vz0 = (iz0 >= 0 && iz0 < 128) ? 1.0f : 0.0f;
    float vz1 = (iz0 + 1 >= 0 && iz0 + 1 < 128) ? 1.0f : 0.0f;

    int x0 = min(max(ix0, 0), 127), x1 = min(max(ix0 + 1, 0), 127);
    int y0 = min(max(iy0, 0), 127), y1 = min(max(iy0 + 1, 0), 127);
    int z0 = min(max(iz0, 0), 127), z1 = min(max(iz0 + 1, 0), 127);

    float wx0 = (1.0f - fx) * vx0, wx1 = fx * vx1;
    float wy0 = (1.0f - fy) * vy0, wy1 = fy * vy1;
    float wz0 = (1.0f - fz) * vz0, wz1 = fz * vz1;

    float acc[16];
#pragma unroll
    for (int c = 0; c < 16; ++c) acc[c] = 0.0f;

    const __half* volBase = g_vol128h + h * 16;

#pragma unroll
    for (int dz = 0; dz < 2; ++dz) {
        int zz = dz ? z1 : z0;
        float wz = dz ? wz1 : wz0;
#pragma unroll
        for (int dy = 0; dy < 2; ++dy) {
            int yy = dy ? y1 : y0;
            float wzy = wz * (dy ? wy1 : wy0);
#pragma unroll
            for (int dx = 0; dx < 2; ++dx) {
                int xx = dx ? x1 : x0;
                float w = wzy * (dx ? wx1 : wx0);
                const uint4* p4 = reinterpret_cast<const uint4*>(
                    volBase + (((size_t)zz * 128 + yy) * 128 + xx) * 32);
                uint4 va = __ldg(p4 + 0);
                uint4 vb = __ldg(p4 + 1);
                acc_pair(acc[0],  acc[1],  va.x, w);
                acc_pair(acc[2],  acc[3],  va.y, w);
                acc_pair(acc[4],  acc[5],  va.z, w);
                acc_pair(acc[6],  acc[7],  va.w, w);
                acc_pair(acc[8],  acc[9],  vb.x, w);
                acc_pair(acc[10], acc[11], vb.y, w);
                acc_pair(acc[12], acc[13], vb.z, w);
                acc_pair(acc[14], acc[15], vb.w, w);   // pad for h=1 (discarded)
            }
        }
    }

    float* row = out + (size_t)n * 28;
    if (h == 0) {
        float4* o4 = reinterpret_cast<float4*>(row);
        o4[0] = make_float4(acc[0],  acc[1],  acc[2],  acc[3]);
        o4[1] = make_float4(acc[4],  acc[5],  acc[6],  acc[7]);
        o4[2] = make_float4(acc[8],  acc[9],  acc[10], acc[11]);
        o4[3] = make_float4(acc[12], acc[13], acc[14], acc[15]);
    } else {
        float4* o4 = reinterpret_cast<float4*>(row + 16);
        o4[0] = make_float4(acc[0],  acc[1],  acc[2],  acc[3]);
        o4[1] = make_float4(acc[4],  acc[5],  acc[6],  acc[7]);
        o4[2] = make_float4(acc[8],  acc[9],  acc[10], acc[11]);
    }
}

extern "C" void kernel_launch(void* const* d_in, const int* in_sizes, int n_in,
                              void* d_out, int out_size) {
    const float* approx = (const float*)d_in[0];
    const float* det0 = (const float*)d_in[1];
    const float* det1 = (const float*)d_in[2];
    const float* det2 = (const float*)d_in[3];
    const float* xyz = (const float*)d_in[4];
    float* out = (float*)d_out;
    int N = in_sizes[4] / 3;

    // IDWT chain
    idwt_cf_kernel<16, true><<<(28 * 16 * 16 * 16 + 255) / 256, 256>>>(approx, det0);
    idwt_cf_kernel<32, false><<<(28 * 32 * 32 * 32 + 255) / 256, 256>>>(nullptr, det1);
    dim3 g2(4, 64, 64);
    idwt_cl_kernel<<<g2, 256>>>(det2);

    // spatial binning (slice-spread counters)
    zero_hist_kernel<<<1, NBINS>>>();
    hist_kernel<<<(N + 255) / 256, 256>>>(xyz, N);
    scan_kernel<<<1, NBINS>>>();
    scatter_kernel<<<(N + 255) / 256, 256>>>(xyz, N);

    // query in binned order
    query_kernel3<<<(N + 127) / 128, 256>>>(out, N);
}